// round 3
// baseline (speedup 1.0000x reference)
#include <cuda_runtime.h>
#include <cuda_bf16.h>

// Problem constants (fixed shapes per reference)
#define NN 100000
#define EE 1600000
#define FIN 32
#define FHID 64
#define FOUT 32

#define SCAN_B 512
#define NB_MAX 256   // ceil(100000/512) = 196 <= 256

// Scratch (device globals — no allocation allowed).
// NOTE: these symbols are ONLY referenced from device code. Passing them as
// kernel arguments from host code silently resolves to the host shadow
// object (ATS-readable on GB300!) — that was the R1/R2 bug.
__device__ int   g_deg[NN];
__device__ int   g_fill[NN];
__device__ int   g_rowptr[NN + 1];
__device__ float g_dinv[NN];
__device__ int   g_col[EE];
__device__ float g_ax[NN * FIN];   // aggregated x  [N,32]
__device__ float g_g[NN * FOUT];   // h@W2 per node [N,32]
__device__ int   g_bsum[NB_MAX];

// Resolved input pointers (set by probe kernel; stream order guarantees visibility)
__device__ const int*   g_eptr;    // edge_index base (src row first)
__device__ const float* g_xptr;    // x base

// ---------------------------------------------------------------------------
// Disambiguate x vs edge_index (both 3.2M elements). Edge indices are all
// unsigned < 100000; fp32 normal values have exponent bits -> huge patterns.
__global__ void k_probe(const void* c0, const void* c1) {
    __shared__ int bad;
    if (threadIdx.x == 0) bad = 0;
    __syncthreads();
    unsigned v = ((const unsigned*)c0)[threadIdx.x * 997];
    if (v >= 100000u) atomicExch(&bad, 1);
    __syncthreads();
    if (threadIdx.x == 0) {
        if (bad == 0) { g_eptr = (const int*)c0; g_xptr = (const float*)c1; }
        else          { g_eptr = (const int*)c1; g_xptr = (const float*)c0; }
    }
}

__global__ void k_zero(int n) {
    int i = blockIdx.x * blockDim.x + threadIdx.x;
    if (i < n) { g_deg[i] = 0; g_fill[i] = 0; }
}

__global__ void k_count(int e) {
    int i = blockIdx.x * blockDim.x + threadIdx.x;
    if (i < e) {
        const int* dst = g_eptr + e;
        int d = dst[i];
        if ((unsigned)d < (unsigned)NN) atomicAdd(&g_deg[d], 1);
    }
}

__global__ void k_dinv(int n) {
    int i = blockIdx.x * blockDim.x + threadIdx.x;
    if (i < n) g_dinv[i] = rsqrtf((float)(g_deg[i] + 1));  // +1 self-loop
}

// ---- exclusive scan of g_deg -> g_rowptr --------------------------------
__global__ void k_scanA(int n) {
    __shared__ int s[SCAN_B];
    int t = threadIdx.x;
    int i = blockIdx.x * SCAN_B + t;
    int v = (i < n) ? g_deg[i] : 0;
    s[t] = v;
    __syncthreads();
    for (int o = 1; o < SCAN_B; o <<= 1) {
        int x = (t >= o) ? s[t - o] : 0;
        __syncthreads();
        s[t] += x;
        __syncthreads();
    }
    if (i < n) g_rowptr[i] = s[t] - v;           // exclusive within block
    if (t == SCAN_B - 1) g_bsum[blockIdx.x] = s[t];
}

__global__ void k_scanB(int nb) {
    __shared__ int s[NB_MAX];
    int t = threadIdx.x;
    int v = (t < nb) ? g_bsum[t] : 0;
    s[t] = v;
    __syncthreads();
    for (int o = 1; o < NB_MAX; o <<= 1) {
        int x = (t >= o) ? s[t - o] : 0;
        __syncthreads();
        s[t] += x;
        __syncthreads();
    }
    if (t < nb) g_bsum[t] = s[t] - v;            // exclusive
}

__global__ void k_scanC(int n, int e) {
    int i = blockIdx.x * blockDim.x + threadIdx.x;
    if (i < n) g_rowptr[i] += g_bsum[i / SCAN_B];
    if (i == 0) g_rowptr[n] = e;
}

// ---- CSR bucket fill -----------------------------------------------------
__global__ void k_fill(int e) {
    int i = blockIdx.x * blockDim.x + threadIdx.x;
    if (i < e) {
        const int* src = g_eptr;
        const int* dst = g_eptr + e;
        int d = dst[i];
        if ((unsigned)d < (unsigned)NN) {
            int pos = g_rowptr[d] + atomicAdd(&g_fill[d], 1);
            g_col[pos] = src[i];
        }
    }
}

// ---- 32-wide normalized aggregation core --------------------------------
// out[v*32+lane] = dinv[v]*sum_u(dinv[u]*in[u*32+lane]) + dinv[v]^2*in[v*32+lane] (+bias)
__device__ __forceinline__ void agg32_body(const float* __restrict__ in,
                                           float* __restrict__ out,
                                           const float* __restrict__ bias,
                                           int n) {
    int warp = (blockIdx.x * blockDim.x + threadIdx.x) >> 5;
    int lane = threadIdx.x & 31;
    if (warp >= n) return;
    int v = warp;
    int beg = g_rowptr[v];
    int end = g_rowptr[v + 1];
    float acc = 0.f;
    int k = beg;
    for (; k + 4 <= end; k += 4) {
        int u0 = g_col[k + 0], u1 = g_col[k + 1], u2 = g_col[k + 2], u3 = g_col[k + 3];
        float w0 = g_dinv[u0], w1 = g_dinv[u1], w2 = g_dinv[u2], w3 = g_dinv[u3];
        float x0 = in[u0 * 32 + lane];
        float x1 = in[u1 * 32 + lane];
        float x2 = in[u2 * 32 + lane];
        float x3 = in[u3 * 32 + lane];
        acc += w0 * x0;
        acc += w1 * x1;
        acc += w2 * x2;
        acc += w3 * x3;
    }
    for (; k < end; k++) {
        int u = g_col[k];
        acc += g_dinv[u] * in[u * 32 + lane];
    }
    float dv = g_dinv[v];
    float r = dv * acc + dv * dv * in[v * 32 + lane];
    if (bias) r += bias[lane];
    out[v * 32 + lane] = r;
}

// Layer-1 aggregation: x (resolved device ptr) -> g_ax (device symbol)
__global__ __launch_bounds__(256) void k_agg_x(int n) {
    agg32_body(g_xptr, g_ax, nullptr, n);
}

// Layer-2 aggregation: g_g (device symbol) -> d_out (harness ptr) + b2
__global__ __launch_bounds__(256) void k_agg_g(float* __restrict__ out,
                                               const float* __restrict__ b2,
                                               int n) {
    agg32_body(g_g, out, b2, n);
}

// ---- fused per-node MLP: g_g = relu(g_ax@W1 + b1) @ W2 -------------------
__global__ __launch_bounds__(256) void k_mlp(const float* __restrict__ W1,
                                             const float* __restrict__ b1,
                                             const float* __restrict__ W2,
                                             int n) {
    __shared__ float sW1[FIN * FHID];   // 32*64
    __shared__ float sW2[FHID * FOUT];  // 64*32
    __shared__ float sb1[FHID];
    for (int i = threadIdx.x; i < FIN * FHID; i += blockDim.x) sW1[i] = W1[i];
    for (int i = threadIdx.x; i < FHID * FOUT; i += blockDim.x) sW2[i] = W2[i];
    if (threadIdx.x < FHID) sb1[threadIdx.x] = b1[threadIdx.x];
    __syncthreads();

    int warp = (blockIdx.x * blockDim.x + threadIdx.x) >> 5;
    int lane = threadIdx.x & 31;
    if (warp >= n) return;

    float xv = g_ax[warp * 32 + lane];
    float h0 = sb1[lane];
    float h1 = sb1[lane + 32];
#pragma unroll
    for (int i = 0; i < 32; i++) {
        float xi = __shfl_sync(0xffffffffu, xv, i);
        h0 = fmaf(xi, sW1[i * 64 + lane], h0);
        h1 = fmaf(xi, sW1[i * 64 + lane + 32], h1);
    }
    h0 = fmaxf(h0, 0.f);
    h1 = fmaxf(h1, 0.f);

    float acc = 0.f;
#pragma unroll
    for (int i = 0; i < 32; i++) {
        float hi = __shfl_sync(0xffffffffu, h0, i);
        acc = fmaf(hi, sW2[i * 32 + lane], acc);
    }
#pragma unroll
    for (int i = 0; i < 32; i++) {
        float hi = __shfl_sync(0xffffffffu, h1, i);
        acc = fmaf(hi, sW2[(i + 32) * 32 + lane], acc);
    }
    g_g[warp * 32 + lane] = acc;
}

// ---------------------------------------------------------------------------
extern "C" void kernel_launch(void* const* d_in, const int* in_sizes, int n_in,
                              void* d_out, int out_size) {
    // Resolve inputs by element count (robust to metadata ordering):
    //   3,200,000 x2 : {x, edge_index}  (disambiguated on-device by k_probe)
    //   2048 x2      : W1 then W2 (W1 precedes W2 in both insertion and
    //                  alphabetical orders)
    //   64 : b1, 32 : b2
    const void* big[2] = {nullptr, nullptr}; int nbig = 0;
    const float* W[2] = {nullptr, nullptr};  int nw = 0;
    const float* b1 = nullptr;
    const float* b2 = nullptr;
    for (int i = 0; i < n_in; i++) {
        int s = in_sizes[i];
        if (s == NN * FIN) { if (nbig < 2) big[nbig++] = d_in[i]; }
        else if (s == FIN * FHID) { if (nw < 2) W[nw++] = (const float*)d_in[i]; }
        else if (s == FHID) b1 = (const float*)d_in[i];
        else if (s == FOUT) b2 = (const float*)d_in[i];
    }
    const float* W1 = W[0];
    const float* W2 = W[1];
    float* out = (float*)d_out;

    const int n = NN;
    const int e = EE;
    int nb = (n + SCAN_B - 1) / SCAN_B;

    k_probe<<<1, 256>>>(big[0], big[1]);
    k_zero<<<(n + 255) / 256, 256>>>(n);
    k_count<<<(e + 255) / 256, 256>>>(e);
    k_dinv<<<(n + 255) / 256, 256>>>(n);
    k_scanA<<<nb, SCAN_B>>>(n);
    k_scanB<<<1, NB_MAX>>>(nb);
    k_scanC<<<(n + 255) / 256, 256>>>(n, e);
    k_fill<<<(e + 255) / 256, 256>>>(e);

    int aggGrid = (n * 32 + 255) / 256;  // warp per node, 8 warps/CTA
    // layer 1: aggregate x (32-wide), then fused MLP (relu(axW1+b1)W2)
    k_agg_x<<<aggGrid, 256>>>(n);
    k_mlp<<<aggGrid, 256>>>(W1, b1, W2, n);
    // layer 2: aggregate g (32-wide) + b2 -> out
    k_agg_g<<<aggGrid, 256>>>(out, b2, n);
}

// round 4
// speedup vs baseline: 1.2844x; 1.2844x over previous
#include <cuda_runtime.h>
#include <cuda_bf16.h>

// Problem constants (fixed shapes per reference)
#define NN 100000
#define EE 1600000
#define FIN 32
#define FHID 64
#define FOUT 32

#define SCAN_B 512
#define NB_MAX 256   // ceil(100000/512) = 196 <= 256

// Scratch (device globals — referenced ONLY from device code; passing them as
// host-side kernel args resolves to the host shadow object on GB300/ATS).
__device__ int   g_deg[NN];
__device__ int   g_fill[NN];
__device__ int   g_rowptr[NN + 1];
__device__ float g_dinv[NN];
__device__ int   g_col[EE];
__device__ float g_xs[NN * FIN];   // dinv[v]*x[v]   (pre-scaled layer-1 input)
__device__ float g_gs[NN * FOUT];  // dinv[v]*(h@W2) (pre-scaled layer-2 input)
__device__ int   g_bsum[NB_MAX];

// Resolved input pointers (set by probe; stream order guarantees visibility)
__device__ const int*   g_eptr;    // edge_index base (src row first)
__device__ const float* g_xptr;    // x base

// ---------------------------------------------------------------------------
// init: zero deg/fill; block 0 also disambiguates x vs edge_index (both 3.2M
// elements). Edge indices are unsigned < 100000; fp32 normals have exponent
// bits set -> bit patterns >= 2^23 almost surely among 256 samples.
__global__ void k_init(const void* c0, const void* c1, int n) {
    int i = blockIdx.x * blockDim.x + threadIdx.x;
    if (i < n) { g_deg[i] = 0; g_fill[i] = 0; }
    if (blockIdx.x == 0) {
        __shared__ int bad;
        if (threadIdx.x == 0) bad = 0;
        __syncthreads();
        unsigned v = ((const unsigned*)c0)[threadIdx.x * 997];
        if (v >= 100000u) atomicExch(&bad, 1);
        __syncthreads();
        if (threadIdx.x == 0) {
            if (bad == 0) { g_eptr = (const int*)c0; g_xptr = (const float*)c1; }
            else          { g_eptr = (const int*)c1; g_xptr = (const float*)c0; }
        }
    }
}

__global__ void k_count(int e) {
    int i = blockIdx.x * blockDim.x + threadIdx.x;
    if (i < e) {
        int d = g_eptr[e + i];
        if ((unsigned)d < (unsigned)NN) atomicAdd(&g_deg[d], 1);
    }
}

// ---- exclusive scan of g_deg -> g_rowptr --------------------------------
__global__ void k_scanA(int n) {
    __shared__ int s[SCAN_B];
    int t = threadIdx.x;
    int i = blockIdx.x * SCAN_B + t;
    int v = (i < n) ? g_deg[i] : 0;
    s[t] = v;
    __syncthreads();
    for (int o = 1; o < SCAN_B; o <<= 1) {
        int x = (t >= o) ? s[t - o] : 0;
        __syncthreads();
        s[t] += x;
        __syncthreads();
    }
    if (i < n) g_rowptr[i] = s[t] - v;           // exclusive within block
    if (t == SCAN_B - 1) g_bsum[blockIdx.x] = s[t];
}

__global__ void k_scanB(int nb) {
    __shared__ int s[NB_MAX];
    int t = threadIdx.x;
    int v = (t < nb) ? g_bsum[t] : 0;
    s[t] = v;
    __syncthreads();
    for (int o = 1; o < NB_MAX; o <<= 1) {
        int x = (t >= o) ? s[t - o] : 0;
        __syncthreads();
        s[t] += x;
        __syncthreads();
    }
    if (t < nb) g_bsum[t] = s[t] - v;            // exclusive
}

__global__ void k_scanC(int n, int e) {
    int i = blockIdx.x * blockDim.x + threadIdx.x;
    if (i < n) g_rowptr[i] += g_bsum[i / SCAN_B];
    if (i == 0) g_rowptr[n] = e;
}

// ---- dinv + pre-scaled xs = dinv[v]*x[v] (float4 per thread) -------------
__global__ void k_prescale(int n) {
    int qi = blockIdx.x * blockDim.x + threadIdx.x;   // quad index, 8 per node
    if (qi < n * 8) {
        int node = qi >> 3;
        float d = rsqrtf((float)(g_deg[node] + 1));   // +1 self-loop
        if ((qi & 7) == 0) g_dinv[node] = d;
        float4 p = ((const float4*)g_xptr)[qi];
        p.x *= d; p.y *= d; p.z *= d; p.w *= d;
        ((float4*)g_xs)[qi] = p;
    }
}

// ---- CSR bucket fill -----------------------------------------------------
__global__ void k_fill(int e) {
    int i = blockIdx.x * blockDim.x + threadIdx.x;
    if (i < e) {
        int d = g_eptr[e + i];
        if ((unsigned)d < (unsigned)NN) {
            int pos = g_rowptr[d] + atomicAdd(&g_fill[d], 1);
            g_col[pos] = g_eptr[i];
        }
    }
}

// ---- float4 warp aggregation core ----------------------------------------
// Warp = node v. lane = eslot(2b)<<3 | fq(3b): 4 edge slots x 8 feature quads.
// Returns lanes 0..7 holding  sum_{u in N(v)} in[u] + in[v]  as float4 (quad fq).
__device__ __forceinline__ float4 agg4(const float* __restrict__ in, int v,
                                       int lane) {
    int beg = g_rowptr[v];
    int end = g_rowptr[v + 1];
    int eslot = lane >> 3;
    int fq = lane & 7;
    float4 acc = make_float4(0.f, 0.f, 0.f, 0.f);
    for (int k = beg; k < end; k += 4) {
        int idx = k + eslot;
        if (idx < end) {
            int u = g_col[idx];
            float4 p = *(const float4*)(in + u * 32 + fq * 4);
            acc.x += p.x; acc.y += p.y; acc.z += p.z; acc.w += p.w;
        }
    }
    if (eslot == 0) {   // self-loop term (pre-scaled input)
        float4 p = *(const float4*)(in + v * 32 + fq * 4);
        acc.x += p.x; acc.y += p.y; acc.z += p.z; acc.w += p.w;
    }
#pragma unroll
    for (int d = 16; d >= 8; d >>= 1) {
        acc.x += __shfl_down_sync(0xffffffffu, acc.x, d);
        acc.y += __shfl_down_sync(0xffffffffu, acc.y, d);
        acc.z += __shfl_down_sync(0xffffffffu, acc.z, d);
        acc.w += __shfl_down_sync(0xffffffffu, acc.w, d);
    }
    return acc;
}

// ---- layer 1 fused: ax = dinv*(agg xs), h = relu(ax@W1+b1), gs = dinv*(h@W2)
__global__ __launch_bounds__(256) void k_l1(const float* __restrict__ W1,
                                            const float* __restrict__ b1,
                                            const float* __restrict__ W2,
                                            int n) {
    __shared__ float sW1[FIN * FHID];   // 8KB
    __shared__ float sW2[FHID * FOUT];  // 8KB
    __shared__ float sb1[FHID];
    __shared__ float s_ax[8][FIN];      // per-warp ax row
    __shared__ float s_h[8][FHID];      // per-warp hidden row
    for (int i = threadIdx.x; i < FIN * FHID; i += blockDim.x) sW1[i] = W1[i];
    for (int i = threadIdx.x; i < FHID * FOUT; i += blockDim.x) sW2[i] = W2[i];
    if (threadIdx.x < FHID) sb1[threadIdx.x] = b1[threadIdx.x];
    __syncthreads();

    int warp = (blockIdx.x * blockDim.x + threadIdx.x) >> 5;
    int wl = threadIdx.x >> 5;
    int lane = threadIdx.x & 31;
    if (warp >= n) return;
    int v = warp;

    float4 acc = agg4(g_xs, v, lane);
    float dv = g_dinv[v];
    if (lane < 8) {
        s_ax[wl][lane * 4 + 0] = dv * acc.x;
        s_ax[wl][lane * 4 + 1] = dv * acc.y;
        s_ax[wl][lane * 4 + 2] = dv * acc.z;
        s_ax[wl][lane * 4 + 3] = dv * acc.w;
    }
    __syncwarp();

    float h0 = sb1[lane];
    float h1 = sb1[lane + 32];
#pragma unroll
    for (int i = 0; i < FIN; i++) {
        float xi = s_ax[wl][i];
        h0 = fmaf(xi, sW1[i * FHID + lane], h0);
        h1 = fmaf(xi, sW1[i * FHID + lane + 32], h1);
    }
    s_h[wl][lane]      = fmaxf(h0, 0.f);
    s_h[wl][lane + 32] = fmaxf(h1, 0.f);
    __syncwarp();

    float o = 0.f;
#pragma unroll
    for (int i = 0; i < FHID; i++)
        o = fmaf(s_h[wl][i], sW2[i * FOUT + lane], o);
    g_gs[v * 32 + lane] = dv * o;      // pre-scaled for layer-2 aggregation
}

// ---- layer 2: out = dinv*(agg gs) + b2 -----------------------------------
__global__ __launch_bounds__(256) void k_l2(float* __restrict__ out,
                                            const float* __restrict__ b2,
                                            int n) {
    int warp = (blockIdx.x * blockDim.x + threadIdx.x) >> 5;
    int lane = threadIdx.x & 31;
    if (warp >= n) return;
    int v = warp;

    float4 acc = agg4(g_gs, v, lane);
    if (lane < 8) {
        float dv = g_dinv[v];
        float4 bq = *(const float4*)(b2 + lane * 4);
        float4 r;
        r.x = dv * acc.x + bq.x;
        r.y = dv * acc.y + bq.y;
        r.z = dv * acc.z + bq.z;
        r.w = dv * acc.w + bq.w;
        *(float4*)(out + v * 32 + lane * 4) = r;
    }
}

// ---------------------------------------------------------------------------
extern "C" void kernel_launch(void* const* d_in, const int* in_sizes, int n_in,
                              void* d_out, int out_size) {
    // Resolve inputs by element count (robust to metadata ordering):
    //   3,200,000 x2 : {x, edge_index} (disambiguated on-device in k_init)
    //   2048 x2      : W1 then W2 ; 64 : b1 ; 32 : b2
    const void* big[2] = {nullptr, nullptr}; int nbig = 0;
    const float* W[2] = {nullptr, nullptr};  int nw = 0;
    const float* b1 = nullptr;
    const float* b2 = nullptr;
    for (int i = 0; i < n_in; i++) {
        int s = in_sizes[i];
        if (s == NN * FIN) { if (nbig < 2) big[nbig++] = d_in[i]; }
        else if (s == FIN * FHID) { if (nw < 2) W[nw++] = (const float*)d_in[i]; }
        else if (s == FHID) b1 = (const float*)d_in[i];
        else if (s == FOUT) b2 = (const float*)d_in[i];
    }
    const float* W1 = W[0];
    const float* W2 = W[1];
    float* out = (float*)d_out;

    const int n = NN;
    const int e = EE;
    int nb = (n + SCAN_B - 1) / SCAN_B;

    k_init<<<(n + 255) / 256, 256>>>(big[0], big[1], n);
    k_count<<<(e + 255) / 256, 256>>>(e);
    k_scanA<<<nb, SCAN_B>>>(n);
    k_scanB<<<1, NB_MAX>>>(nb);
    k_prescale<<<(n * 8 + 255) / 256, 256>>>(n);
    k_scanC<<<(n + 255) / 256, 256>>>(n, e);
    k_fill<<<(e + 255) / 256, 256>>>(e);

    int aggGrid = (n * 32 + 255) / 256;  // warp per node, 8 warps/CTA
    k_l1<<<aggGrid, 256>>>(W1, b1, W2, n);
    k_l2<<<aggGrid, 256>>>(out, b2, n);
}

// round 5
// speedup vs baseline: 1.3071x; 1.0177x over previous
#include <cuda_runtime.h>
#include <cuda_fp16.h>

// Problem constants (fixed shapes per reference)
#define NN 100000
#define EE 1600000
#define FIN 32
#define FHID 64
#define FOUT 32

#define SCAN_B 512
#define NB 196            // ceil(100000/512)
#define NB_MAX 256

// Scratch (device globals — referenced ONLY from device code; passing them as
// host-side kernel args resolves to the host shadow object on GB300/ATS).
__device__ int    g_deg[NN];
__device__ int    g_rowptr[NN];        // block-local exclusive prefix of deg
__device__ int    g_cur[NN];           // fill cursor, initialized = g_rowptr
__device__ int    g_bsum[NB_MAX];      // per-block sums -> exclusive after scanB
__device__ float  g_dinv[NN];
__device__ int    g_col[EE];
__device__ __align__(16) __half g_xsh[NN * FIN];   // dinv[v]*x[v]    (fp16)
__device__ __align__(16) __half g_gsh[NN * FOUT];  // dinv[v]*(h@W2)  (fp16)

// ---------------------------------------------------------------------------
// Per-warp inline probe: which of {c0,c1} is edge_index? Edge words are
// unsigned < 100000; fp32 normal bit patterns are >= 2^23 (or sign bit set)
// except for |x| < 1.4e-40 (measure-zero). 32 samples, warp-uniform verdict.
__device__ __forceinline__ int probe_is_edges(const void* c0) {
    unsigned idx = (threadIdx.x & 31) * 99991u + (blockIdx.x & 1023) * 131u;
    unsigned v = ((const unsigned*)c0)[idx];  // < 3.2M
    return __all_sync(0xffffffffu, v < 100000u);
}

__global__ void k_zero(int n) {
    int i = blockIdx.x * blockDim.x + threadIdx.x;
    if (i < n) g_deg[i] = 0;
}

__global__ void k_count(const void* c0, const void* c1, int e) {
    const int* eptr = probe_is_edges(c0) ? (const int*)c0 : (const int*)c1;
    int i = blockIdx.x * blockDim.x + threadIdx.x;
    if (i < e) {
        int d = eptr[e + i];
        if ((unsigned)d < (unsigned)NN) atomicAdd(&g_deg[d], 1);
    }
}

// ---- scanA: block-exclusive scan of deg + dinv + fp16 pre-scaled features
__global__ __launch_bounds__(SCAN_B) void k_scanA(const void* c0, const void* c1,
                                                  int n) {
    const float* xptr = probe_is_edges(c0) ? (const float*)c1 : (const float*)c0;
    __shared__ int   s[SCAN_B];
    __shared__ float sdinv[SCAN_B];
    int t = threadIdx.x;
    int i = blockIdx.x * SCAN_B + t;
    int v = (i < n) ? g_deg[i] : 0;
    s[t] = v;
    __syncthreads();
    for (int o = 1; o < SCAN_B; o <<= 1) {
        int x = (t >= o) ? s[t - o] : 0;
        __syncthreads();
        s[t] += x;
        __syncthreads();
    }
    float d = rsqrtf((float)(v + 1));          // +1 self-loop
    if (i < n) {
        int excl = s[t] - v;
        g_rowptr[i] = excl;
        g_cur[i] = excl;                        // fill cursor (no zero needed)
        g_dinv[i] = d;
    }
    sdinv[t] = d;
    if (t == SCAN_B - 1) g_bsum[blockIdx.x] = s[t];
    __syncthreads();

    // pre-scale: nodes [b0, b0+512) -> fp16 rows (4096 quads, 8 iters)
    int b0 = blockIdx.x * SCAN_B;
#pragma unroll
    for (int r = 0; r < 8; r++) {
        int ql = t + r * SCAN_B;               // local quad 0..4095
        int nl = ql >> 3;                      // local node
        int node = b0 + nl;
        if (node < n) {
            float4 p = ((const float4*)xptr)[node * 8 + (ql & 7)];
            float dd = sdinv[nl];
            __half2 h0 = __floats2half2_rn(p.x * dd, p.y * dd);
            __half2 h1 = __floats2half2_rn(p.z * dd, p.w * dd);
            uint2 packed;
            packed.x = *(unsigned*)&h0;
            packed.y = *(unsigned*)&h1;
            ((uint2*)g_xsh)[node * 8 + (ql & 7)] = packed;
        }
    }
}

__global__ void k_scanB(int nb) {
    __shared__ int s[NB_MAX];
    int t = threadIdx.x;
    int v = (t < nb) ? g_bsum[t] : 0;
    s[t] = v;
    __syncthreads();
    for (int o = 1; o < NB_MAX; o <<= 1) {
        int x = (t >= o) ? s[t - o] : 0;
        __syncthreads();
        s[t] += x;
        __syncthreads();
    }
    if (t < nb) g_bsum[t] = s[t] - v;           // exclusive block offsets
}

// global rowptr on the fly
__device__ __forceinline__ int rp(int i, int e) {
    return (i == NN) ? e : (g_rowptr[i] + g_bsum[i >> 9]);
}

// ---- CSR bucket fill -----------------------------------------------------
__global__ void k_fill(const void* c0, const void* c1, int e) {
    const int* eptr = probe_is_edges(c0) ? (const int*)c0 : (const int*)c1;
    int i = blockIdx.x * blockDim.x + threadIdx.x;
    if (i < e) {
        int d = eptr[e + i];
        if ((unsigned)d < (unsigned)NN) {
            int pos = atomicAdd(&g_cur[d], 1) + g_bsum[d >> 9];
            g_col[pos] = eptr[i];
        }
    }
}

// ---- fp16 warp aggregation core ------------------------------------------
// Warp = node v. lane = eslot(2b)<<3 | fq(3b): 4 edge slots x 8 feature quads.
// Lane loads 4 halves (8B). After reduce, lanes 0..7 hold quad fq as float4:
//   sum_{u in N(v)} in[u] + in[v]        (inputs pre-scaled by dinv[u])
__device__ __forceinline__ float4 aggh(const __half* __restrict__ in,
                                       int v, int lane, int beg, int end) {
    int eslot = lane >> 3;
    int fq = lane & 7;
    float4 acc = make_float4(0.f, 0.f, 0.f, 0.f);
    for (int k = beg; k < end; k += 4) {
        int idx = k + eslot;
        if (idx < end) {
            int u = g_col[idx];
            uint2 raw = *(const uint2*)(in + u * 32 + fq * 4);
            float2 fa = __half22float2(*(__half2*)&raw.x);
            float2 fb = __half22float2(*(__half2*)&raw.y);
            acc.x += fa.x; acc.y += fa.y; acc.z += fb.x; acc.w += fb.y;
        }
    }
    if (eslot == 0) {   // self-loop
        uint2 raw = *(const uint2*)(in + v * 32 + fq * 4);
        float2 fa = __half22float2(*(__half2*)&raw.x);
        float2 fb = __half22float2(*(__half2*)&raw.y);
        acc.x += fa.x; acc.y += fa.y; acc.z += fb.x; acc.w += fb.y;
    }
#pragma unroll
    for (int d = 16; d >= 8; d >>= 1) {
        acc.x += __shfl_down_sync(0xffffffffu, acc.x, d);
        acc.y += __shfl_down_sync(0xffffffffu, acc.y, d);
        acc.z += __shfl_down_sync(0xffffffffu, acc.z, d);
        acc.w += __shfl_down_sync(0xffffffffu, acc.w, d);
    }
    return acc;
}

// ---- layer 1 fused: ax = dinv*(agg xs); h = relu(ax@W1+b1); gs = dinv*(h@W2)
__global__ __launch_bounds__(256) void k_l1(const float* __restrict__ W1,
                                            const float* __restrict__ b1,
                                            const float* __restrict__ W2,
                                            int n, int e) {
    __shared__ float sW1[FIN * FHID];
    __shared__ float sW2[FHID * FOUT];
    __shared__ float sb1[FHID];
    __shared__ float s_ax[8][FIN];
    __shared__ float s_h[8][FHID];
    for (int i = threadIdx.x; i < FIN * FHID; i += blockDim.x) sW1[i] = W1[i];
    for (int i = threadIdx.x; i < FHID * FOUT; i += blockDim.x) sW2[i] = W2[i];
    if (threadIdx.x < FHID) sb1[threadIdx.x] = b1[threadIdx.x];
    __syncthreads();

    int warp = (blockIdx.x * blockDim.x + threadIdx.x) >> 5;
    int wl = threadIdx.x >> 5;
    int lane = threadIdx.x & 31;
    if (warp >= n) return;
    int v = warp;

    float4 acc = aggh(g_xsh, v, lane, rp(v, e), rp(v + 1, e));
    float dv = g_dinv[v];
    if (lane < 8) {
        s_ax[wl][lane * 4 + 0] = dv * acc.x;
        s_ax[wl][lane * 4 + 1] = dv * acc.y;
        s_ax[wl][lane * 4 + 2] = dv * acc.z;
        s_ax[wl][lane * 4 + 3] = dv * acc.w;
    }
    __syncwarp();

    float h0 = sb1[lane];
    float h1 = sb1[lane + 32];
#pragma unroll
    for (int i = 0; i < FIN; i++) {
        float xi = s_ax[wl][i];
        h0 = fmaf(xi, sW1[i * FHID + lane], h0);
        h1 = fmaf(xi, sW1[i * FHID + lane + 32], h1);
    }
    s_h[wl][lane]      = fmaxf(h0, 0.f);
    s_h[wl][lane + 32] = fmaxf(h1, 0.f);
    __syncwarp();

    float o = 0.f;
#pragma unroll
    for (int i = 0; i < FHID; i++)
        o = fmaf(s_h[wl][i], sW2[i * FOUT + lane], o);
    g_gsh[v * 32 + lane] = __float2half_rn(dv * o);   // pre-scaled, fp16
}

// ---- layer 2: out = dinv*(agg gs) + b2 -----------------------------------
__global__ __launch_bounds__(256) void k_l2(float* __restrict__ out,
                                            const float* __restrict__ b2,
                                            int n, int e) {
    int warp = (blockIdx.x * blockDim.x + threadIdx.x) >> 5;
    int lane = threadIdx.x & 31;
    if (warp >= n) return;
    int v = warp;

    float4 acc = aggh(g_gsh, v, lane, rp(v, e), rp(v + 1, e));
    if (lane < 8) {
        float dv = g_dinv[v];
        float4 bq = *(const float4*)(b2 + lane * 4);
        float4 r;
        r.x = dv * acc.x + bq.x;
        r.y = dv * acc.y + bq.y;
        r.z = dv * acc.z + bq.z;
        r.w = dv * acc.w + bq.w;
        *(float4*)(out + v * 32 + lane * 4) = r;
    }
}

// ---------------------------------------------------------------------------
extern "C" void kernel_launch(void* const* d_in, const int* in_sizes, int n_in,
                              void* d_out, int out_size) {
    // Resolve by element count: 3.2M x2 {x, edge_index} (probed on-device);
    // 2048 x2 W1 then W2; 64 b1; 32 b2.
    const void* big[2] = {nullptr, nullptr}; int nbig = 0;
    const float* W[2] = {nullptr, nullptr};  int nw = 0;
    const float* b1 = nullptr;
    const float* b2 = nullptr;
    for (int i = 0; i < n_in; i++) {
        int s = in_sizes[i];
        if (s == NN * FIN) { if (nbig < 2) big[nbig++] = d_in[i]; }
        else if (s == FIN * FHID) { if (nw < 2) W[nw++] = (const float*)d_in[i]; }
        else if (s == FHID) b1 = (const float*)d_in[i];
        else if (s == FOUT) b2 = (const float*)d_in[i];
    }
    const float* W1 = W[0];
    const float* W2 = W[1];
    float* out = (float*)d_out;

    const int n = NN;
    const int e = EE;
    int nb = (n + SCAN_B - 1) / SCAN_B;   // 196

    k_zero<<<(n + 255) / 256, 256>>>(n);
    k_count<<<(e + 255) / 256, 256>>>(big[0], big[1], e);
    k_scanA<<<nb, SCAN_B>>>(big[0], big[1], n);
    k_scanB<<<1, NB_MAX>>>(nb);
    k_fill<<<(e + 255) / 256, 256>>>(big[0], big[1], e);

    int aggGrid = (n * 32 + 255) / 256;   // warp per node, 8 warps/CTA
    k_l1<<<aggGrid, 256>>>(W1, b1, W2, n, e);
    k_l2<<<aggGrid, 256>>>(out, b2, n, e);
}

// round 6
// speedup vs baseline: 1.3385x; 1.0240x over previous
#include <cuda_runtime.h>
#include <cuda_fp16.h>

// Problem constants (fixed shapes per reference)
#define NN 100000
#define EE 1600000
#define FIN 32
#define FHID 64
#define FOUT 32

#define SCAN_B 512
#define NB_MAX 256   // ceil(100000/512)=196 <= 256

// Scratch (device globals — referenced ONLY from device code; host-side use of
// these symbols resolves to the host shadow object on GB300/ATS).
__device__ int    g_deg[NN];
__device__ int    g_rowptr[NN];        // block-local exclusive prefix of deg
__device__ int    g_cur[NN];           // fill cursor, initialized = g_rowptr
__device__ int    g_bsum[NB_MAX];      // per-block sums -> exclusive after last-block scan
__device__ float  g_dinv[NN];
__device__ int    g_col[EE];
__device__ int    g_scan_done = 0;     // last-block ticket (self-resetting)
__device__ __align__(16) __half g_xsh[NN * FIN];   // dinv[v]*x[v]    (fp16)
__device__ __align__(16) __half g_gsh[NN * FOUT];  // dinv[v]*(h@W2)  (fp16)

// packed f32x2 fma
#define FMA2(d, a, b, c) \
    asm("fma.rn.f32x2 %0, %1, %2, %3;" : "=l"(d) : "l"(a), "l"(b), "l"(c))

// ---------------------------------------------------------------------------
// Per-warp inline probe: which of {c0,c1} is edge_index? Edge words are
// unsigned < 100000; fp32 normal bit patterns are >= 2^23 or have sign bit.
__device__ __forceinline__ int probe_is_edges(const void* c0) {
    unsigned idx = (threadIdx.x & 31) * 99991u + (blockIdx.x & 1023) * 131u;
    unsigned v = ((const unsigned*)c0)[idx];  // < 3.2M
    return __all_sync(0xffffffffu, v < 100000u);
}

// ---- degree count: 4 edges per thread (int4) ------------------------------
__global__ void k_count(const void* c0, const void* c1, int e) {
    const int* eptr = probe_is_edges(c0) ? (const int*)c0 : (const int*)c1;
    int i = (blockIdx.x * blockDim.x + threadIdx.x) * 4;
    if (i < e) {
        int4 d4 = *(const int4*)(eptr + e + i);
        if ((unsigned)d4.x < (unsigned)NN) atomicAdd(&g_deg[d4.x], 1);
        if ((unsigned)d4.y < (unsigned)NN) atomicAdd(&g_deg[d4.y], 1);
        if ((unsigned)d4.z < (unsigned)NN) atomicAdd(&g_deg[d4.z], 1);
        if ((unsigned)d4.w < (unsigned)NN) atomicAdd(&g_deg[d4.w], 1);
    }
}

// ---- scan: block-exclusive scan of deg + dinv + fp16 pre-scale; the last
// block to finish also scans the 196 block sums (replaces scanB launch).
__global__ __launch_bounds__(SCAN_B) void k_scan(const void* c0, const void* c1,
                                                 int n, int nb) {
    const float* xptr = probe_is_edges(c0) ? (const float*)c1 : (const float*)c0;
    __shared__ int   s[SCAN_B];
    __shared__ float sdinv[SCAN_B];
    __shared__ int   sB[NB_MAX];
    __shared__ bool  amLast;
    int t = threadIdx.x;
    int i = blockIdx.x * SCAN_B + t;
    int v = (i < n) ? g_deg[i] : 0;
    s[t] = v;
    __syncthreads();
    for (int o = 1; o < SCAN_B; o <<= 1) {
        int x = (t >= o) ? s[t - o] : 0;
        __syncthreads();
        s[t] += x;
        __syncthreads();
    }
    float d = rsqrtf((float)(v + 1));          // +1 self-loop
    if (i < n) {
        int excl = s[t] - v;
        g_rowptr[i] = excl;
        g_cur[i] = excl;                        // fill cursor
        g_dinv[i] = d;
    }
    sdinv[t] = d;
    if (t == SCAN_B - 1) g_bsum[blockIdx.x] = s[t];
    __syncthreads();

    // pre-scale: nodes [b0, b0+512) -> fp16 rows (4096 quads, 8 iters)
    int b0 = blockIdx.x * SCAN_B;
#pragma unroll
    for (int r = 0; r < 8; r++) {
        int ql = t + r * SCAN_B;               // local quad 0..4095
        int nl = ql >> 3;                      // local node
        int node = b0 + nl;
        if (node < n) {
            float4 p = ((const float4*)xptr)[node * 8 + (ql & 7)];
            float dd = sdinv[nl];
            __half2 h0 = __floats2half2_rn(p.x * dd, p.y * dd);
            __half2 h1 = __floats2half2_rn(p.z * dd, p.w * dd);
            uint2 packed;
            packed.x = *(unsigned*)&h0;
            packed.y = *(unsigned*)&h1;
            ((uint2*)g_xsh)[node * 8 + (ql & 7)] = packed;
        }
    }

    // last-block: exclusive scan of the nb block sums
    __threadfence();
    __syncthreads();
    if (t == 0) amLast = (atomicAdd(&g_scan_done, 1) == gridDim.x - 1);
    __syncthreads();
    if (amLast) {
        __threadfence();                        // acquire all bsum writes
        int bv = (t < NB_MAX && t < nb) ? g_bsum[t] : 0;
        if (t < NB_MAX) sB[t] = bv;
        __syncthreads();
        for (int o = 1; o < NB_MAX; o <<= 1) {
            int x = (t >= o && t < NB_MAX) ? sB[t - o] : 0;
            __syncthreads();
            if (t < NB_MAX) sB[t] += x;
            __syncthreads();
        }
        if (t < nb) g_bsum[t] = sB[t] - bv;     // exclusive block offsets
        if (t == 0) g_scan_done = 0;            // reset for next graph replay
    }
}

// global rowptr on the fly
__device__ __forceinline__ int rp(int i, int e) {
    return (i == NN) ? e : (g_rowptr[i] + g_bsum[i >> 9]);
}

// ---- CSR bucket fill: 4 edges per thread ----------------------------------
__global__ void k_fill(const void* c0, const void* c1, int e) {
    const int* eptr = probe_is_edges(c0) ? (const int*)c0 : (const int*)c1;
    int i = (blockIdx.x * blockDim.x + threadIdx.x) * 4;
    if (i < e) {
        int4 s4 = *(const int4*)(eptr + i);
        int4 d4 = *(const int4*)(eptr + e + i);
        if ((unsigned)d4.x < (unsigned)NN)
            g_col[atomicAdd(&g_cur[d4.x], 1) + g_bsum[d4.x >> 9]] = s4.x;
        if ((unsigned)d4.y < (unsigned)NN)
            g_col[atomicAdd(&g_cur[d4.y], 1) + g_bsum[d4.y >> 9]] = s4.y;
        if ((unsigned)d4.z < (unsigned)NN)
            g_col[atomicAdd(&g_cur[d4.z], 1) + g_bsum[d4.z >> 9]] = s4.z;
        if ((unsigned)d4.w < (unsigned)NN)
            g_col[atomicAdd(&g_cur[d4.w], 1) + g_bsum[d4.w >> 9]] = s4.w;
    }
}

// ---- fp16 warp aggregation core: 8 edges in flight per iteration ----------
// Warp = node v. lane = eslot(2b)<<3 | fq(3b). Per iter each lane issues two
// independent col loads and two independent 8B gathers (chain depth 2, MLP 4).
// After reduce, lanes 0..7 hold quad fq of  sum_{u in N(v)} in[u] + in[v].
__device__ __forceinline__ float4 aggh(const __half* __restrict__ in,
                                       int v, int lane, int beg, int end) {
    int eslot = lane >> 3;
    int fq = lane & 7;
    float4 acc = make_float4(0.f, 0.f, 0.f, 0.f);
    for (int k = beg; k < end; k += 8) {
        int i0 = k + eslot;
        int i1 = k + 4 + eslot;
        int u0 = (i0 < end) ? g_col[i0] : -1;
        int u1 = (i1 < end) ? g_col[i1] : -1;
        if (u0 >= 0) {
            uint2 raw = *(const uint2*)(in + u0 * 32 + fq * 4);
            float2 fa = __half22float2(*(__half2*)&raw.x);
            float2 fb = __half22float2(*(__half2*)&raw.y);
            acc.x += fa.x; acc.y += fa.y; acc.z += fb.x; acc.w += fb.y;
        }
        if (u1 >= 0) {
            uint2 raw = *(const uint2*)(in + u1 * 32 + fq * 4);
            float2 fa = __half22float2(*(__half2*)&raw.x);
            float2 fb = __half22float2(*(__half2*)&raw.y);
            acc.x += fa.x; acc.y += fa.y; acc.z += fb.x; acc.w += fb.y;
        }
    }
    if (eslot == 0) {   // self-loop
        uint2 raw = *(const uint2*)(in + v * 32 + fq * 4);
        float2 fa = __half22float2(*(__half2*)&raw.x);
        float2 fb = __half22float2(*(__half2*)&raw.y);
        acc.x += fa.x; acc.y += fa.y; acc.z += fb.x; acc.w += fb.y;
    }
#pragma unroll
    for (int d = 16; d >= 8; d >>= 1) {
        acc.x += __shfl_down_sync(0xffffffffu, acc.x, d);
        acc.y += __shfl_down_sync(0xffffffffu, acc.y, d);
        acc.z += __shfl_down_sync(0xffffffffu, acc.z, d);
        acc.w += __shfl_down_sync(0xffffffffu, acc.w, d);
    }
    return acc;
}

// ---- layer 1 fused: ax = dinv*(agg xs); h = relu(ax@W1+b1); gs = dinv*(h@W2)
// MLP uses packed fma.rn.f32x2 with pre-paired weights in smem.
__global__ __launch_bounds__(256) void k_l1(const float* __restrict__ W1,
                                            const float* __restrict__ b1,
                                            const float* __restrict__ W2,
                                            int n, int e) {
    __shared__ unsigned long long sW1p[FIN * 32];   // (W1[i][l], W1[i][l+32])
    __shared__ unsigned long long sW2p[32 * 32];    // (W2[2i][l], W2[2i+1][l])
    __shared__ unsigned long long sb1p[32];         // (b1[l], b1[l+32])
    __shared__ float s_ax[8][FIN];
    __shared__ float s_h[8][FHID];
    for (int idx = threadIdx.x; idx < 1024; idx += blockDim.x) {
        int i = idx >> 5, l = idx & 31;
        // both W1 and W2 pair as (W[i*64+l], W[i*64+32+l])
        float2 a = make_float2(W1[i * 64 + l], W1[i * 64 + 32 + l]);
        float2 b = make_float2(W2[i * 64 + l], W2[i * 64 + 32 + l]);
        sW1p[idx] = *(unsigned long long*)&a;
        sW2p[idx] = *(unsigned long long*)&b;
    }
    if (threadIdx.x < 32) {
        float2 bb = make_float2(b1[threadIdx.x], b1[threadIdx.x + 32]);
        sb1p[threadIdx.x] = *(unsigned long long*)&bb;
    }
    __syncthreads();

    int warp = (blockIdx.x * blockDim.x + threadIdx.x) >> 5;
    int wl = threadIdx.x >> 5;
    int lane = threadIdx.x & 31;
    if (warp >= n) return;
    int v = warp;

    float4 acc = aggh(g_xsh, v, lane, rp(v, e), rp(v + 1, e));
    float dv = g_dinv[v];
    if (lane < 8) {
        s_ax[wl][lane * 4 + 0] = dv * acc.x;
        s_ax[wl][lane * 4 + 1] = dv * acc.y;
        s_ax[wl][lane * 4 + 2] = dv * acc.z;
        s_ax[wl][lane * 4 + 3] = dv * acc.w;
    }
    __syncwarp();

    // layer 1: packed (h0,h1) accumulate
    unsigned long long acc01 = sb1p[lane];
#pragma unroll
    for (int i = 0; i < FIN; i++) {
        float xi = s_ax[wl][i];
        unsigned long long xi2;
        asm("mov.b64 %0, {%1, %1};" : "=l"(xi2) : "r"(__float_as_uint(xi)));
        FMA2(acc01, xi2, sW1p[i * 32 + lane], acc01);
    }
    float h0 = __uint_as_float((unsigned)(acc01 & 0xffffffffull));
    float h1 = __uint_as_float((unsigned)(acc01 >> 32));
    s_h[wl][lane]      = fmaxf(h0, 0.f);
    s_h[wl][lane + 32] = fmaxf(h1, 0.f);
    __syncwarp();

    // layer 2: packed pair-sum over hidden dim
    unsigned long long acc2 = 0;
#pragma unroll
    for (int i = 0; i < 32; i++) {
        unsigned long long hp = *(const unsigned long long*)&s_h[wl][2 * i];
        FMA2(acc2, hp, sW2p[i * 32 + lane], acc2);
    }
    float o = __uint_as_float((unsigned)(acc2 & 0xffffffffull)) +
              __uint_as_float((unsigned)(acc2 >> 32));
    g_gsh[v * 32 + lane] = __float2half_rn(dv * o);   // pre-scaled, fp16
}

// ---- layer 2: out = dinv*(agg gs) + b2 -----------------------------------
__global__ __launch_bounds__(256) void k_l2(float* __restrict__ out,
                                            const float* __restrict__ b2,
                                            int n, int e) {
    int warp = (blockIdx.x * blockDim.x + threadIdx.x) >> 5;
    int lane = threadIdx.x & 31;
    if (warp >= n) return;
    int v = warp;

    float4 acc = aggh(g_gsh, v, lane, rp(v, e), rp(v + 1, e));
    if (lane < 8) {
        float dv = g_dinv[v];
        float4 bq = *(const float4*)(b2 + lane * 4);
        float4 r;
        r.x = dv * acc.x + bq.x;
        r.y = dv * acc.y + bq.y;
        r.z = dv * acc.z + bq.z;
        r.w = dv * acc.w + bq.w;
        *(float4*)(out + v * 32 + lane * 4) = r;
    }
}

// ---------------------------------------------------------------------------
extern "C" void kernel_launch(void* const* d_in, const int* in_sizes, int n_in,
                              void* d_out, int out_size) {
    // Resolve by element count: 3.2M x2 {x, edge_index} (probed on-device);
    // 2048 x2 W1 then W2; 64 b1; 32 b2.
    const void* big[2] = {nullptr, nullptr}; int nbig = 0;
    const float* W[2] = {nullptr, nullptr};  int nw = 0;
    const float* b1 = nullptr;
    const float* b2 = nullptr;
    for (int i = 0; i < n_in; i++) {
        int s = in_sizes[i];
        if (s == NN * FIN) { if (nbig < 2) big[nbig++] = d_in[i]; }
        else if (s == FIN * FHID) { if (nw < 2) W[nw++] = (const float*)d_in[i]; }
        else if (s == FHID) b1 = (const float*)d_in[i];
        else if (s == FOUT) b2 = (const float*)d_in[i];
    }
    const float* W1 = W[0];
    const float* W2 = W[1];
    float* out = (float*)d_out;

    const int n = NN;
    const int e = EE;
    int nb = (n + SCAN_B - 1) / SCAN_B;   // 196

    // zero g_deg via memset node (true device address, NOT the host shadow)
    void* degAddr = nullptr;
    cudaGetSymbolAddress(&degAddr, g_deg);
    cudaMemsetAsync(degAddr, 0, NN * sizeof(int));

    int eThreads = e / 4;
    k_count<<<(eThreads + 255) / 256, 256>>>(big[0], big[1], e);
    k_scan<<<nb, SCAN_B>>>(big[0], big[1], n, nb);
    k_fill<<<(eThreads + 255) / 256, 256>>>(big[0], big[1], e);

    int aggGrid = (n * 32 + 255) / 256;   // warp per node, 8 warps/CTA
    k_l1<<<aggGrid, 256>>>(W1, b1, W2, n, e);
    k_l2<<<aggGrid, 256>>>(out, b2, n, e);
}

// round 7
// speedup vs baseline: 1.4188x; 1.0600x over previous
#include <cuda_runtime.h>
#include <cuda_fp16.h>

// Problem constants (fixed shapes per reference)
#define NN 100000
#define EE 1600000
#define FIN 32
#define FHID 64
#define FOUT 32

#define SCAN_B 512
#define NB_MAX 256   // ceil(100000/512)=196 <= 256
#define TILE_W 8     // nodes per warp in k_l1

// Scratch (device globals — referenced ONLY from device code; host-side use of
// these symbols resolves to the host shadow object on GB300/ATS).
__device__ int    g_deg[NN];
__device__ int    g_rowptr[NN];        // block-local exclusive prefix of deg
__device__ int    g_cur[NN];           // fill cursor, initialized = g_rowptr
__device__ int    g_bsum[NB_MAX];      // per-block sums -> exclusive after last-block scan
__device__ float  g_dinv[NN];
__device__ int    g_col[EE];
__device__ int    g_scan_done = 0;     // last-block ticket (self-resetting)
__device__ __align__(16) __half g_xsh[NN * FIN];   // dinv[v]*x[v]    (fp16)
__device__ __align__(16) __half g_gsh[NN * FOUT];  // dinv[v]*(h@W2)  (fp16)

// packed f32x2 helpers
#define FMA2(d, a, b, c) \
    asm("fma.rn.f32x2 %0, %1, %2, %3;" : "=l"(d) : "l"(a), "l"(b), "l"(c))
__device__ __forceinline__ unsigned long long pk2(float a, float b) {
    float2 t = make_float2(a, b);
    return *(unsigned long long*)&t;
}
__device__ __forceinline__ unsigned long long dup2(float a) {
    unsigned long long r;
    asm("mov.b64 %0, {%1, %1};" : "=l"(r) : "r"(__float_as_uint(a)));
    return r;
}
__device__ __forceinline__ float lo2(unsigned long long v) {
    return __uint_as_float((unsigned)(v & 0xffffffffull));
}
__device__ __forceinline__ float hi2(unsigned long long v) {
    return __uint_as_float((unsigned)(v >> 32));
}

// ---------------------------------------------------------------------------
// Per-warp inline probe: which of {c0,c1} is edge_index? Edge words are
// unsigned < 100000; fp32 normal bit patterns are >= 2^23 or have sign bit.
__device__ __forceinline__ int probe_is_edges(const void* c0) {
    unsigned idx = (threadIdx.x & 31) * 99991u + (blockIdx.x & 1023) * 131u;
    unsigned v = ((const unsigned*)c0)[idx];  // < 3.2M
    return __all_sync(0xffffffffu, v < 100000u);
}

// ---- degree count: 4 edges per thread (int4) ------------------------------
__global__ void k_count(const void* c0, const void* c1, int e) {
    const int* eptr = probe_is_edges(c0) ? (const int*)c0 : (const int*)c1;
    int i = (blockIdx.x * blockDim.x + threadIdx.x) * 4;
    if (i < e) {
        int4 d4 = *(const int4*)(eptr + e + i);
        if ((unsigned)d4.x < (unsigned)NN) atomicAdd(&g_deg[d4.x], 1);
        if ((unsigned)d4.y < (unsigned)NN) atomicAdd(&g_deg[d4.y], 1);
        if ((unsigned)d4.z < (unsigned)NN) atomicAdd(&g_deg[d4.z], 1);
        if ((unsigned)d4.w < (unsigned)NN) atomicAdd(&g_deg[d4.w], 1);
    }
}

// ---- scan: block-exclusive scan of deg + dinv + fp16 pre-scale; the last
// block to finish also scans the 196 block sums (fused scanB).
__global__ __launch_bounds__(SCAN_B) void k_scan(const void* c0, const void* c1,
                                                 int n, int nb) {
    const float* xptr = probe_is_edges(c0) ? (const float*)c1 : (const float*)c0;
    __shared__ int   s[SCAN_B];
    __shared__ float sdinv[SCAN_B];
    __shared__ int   sB[NB_MAX];
    __shared__ bool  amLast;
    int t = threadIdx.x;
    int i = blockIdx.x * SCAN_B + t;
    int v = (i < n) ? g_deg[i] : 0;
    s[t] = v;
    __syncthreads();
    for (int o = 1; o < SCAN_B; o <<= 1) {
        int x = (t >= o) ? s[t - o] : 0;
        __syncthreads();
        s[t] += x;
        __syncthreads();
    }
    float d = rsqrtf((float)(v + 1));          // +1 self-loop
    if (i < n) {
        int excl = s[t] - v;
        g_rowptr[i] = excl;
        g_cur[i] = excl;                        // fill cursor
        g_dinv[i] = d;
    }
    sdinv[t] = d;
    if (t == SCAN_B - 1) g_bsum[blockIdx.x] = s[t];
    __syncthreads();

    // pre-scale: nodes [b0, b0+512) -> fp16 rows (4096 quads, 8 iters)
    int b0 = blockIdx.x * SCAN_B;
#pragma unroll
    for (int r = 0; r < 8; r++) {
        int ql = t + r * SCAN_B;               // local quad 0..4095
        int nl = ql >> 3;                      // local node
        int node = b0 + nl;
        if (node < n) {
            float4 p = ((const float4*)xptr)[node * 8 + (ql & 7)];
            float dd = sdinv[nl];
            __half2 h0 = __floats2half2_rn(p.x * dd, p.y * dd);
            __half2 h1 = __floats2half2_rn(p.z * dd, p.w * dd);
            uint2 packed;
            packed.x = *(unsigned*)&h0;
            packed.y = *(unsigned*)&h1;
            ((uint2*)g_xsh)[node * 8 + (ql & 7)] = packed;
        }
    }

    // last-block: exclusive scan of the nb block sums
    __threadfence();
    __syncthreads();
    if (t == 0) amLast = (atomicAdd(&g_scan_done, 1) == gridDim.x - 1);
    __syncthreads();
    if (amLast) {
        __threadfence();                        // acquire all bsum writes
        int bv = (t < NB_MAX && t < nb) ? g_bsum[t] : 0;
        if (t < NB_MAX) sB[t] = bv;
        __syncthreads();
        for (int o = 1; o < NB_MAX; o <<= 1) {
            int x = (t >= o && t < NB_MAX) ? sB[t - o] : 0;
            __syncthreads();
            if (t < NB_MAX) sB[t] += x;
            __syncthreads();
        }
        if (t < nb) g_bsum[t] = sB[t] - bv;     // exclusive block offsets
        if (t == 0) g_scan_done = 0;            // reset for next graph replay
    }
}

// global rowptr on the fly
__device__ __forceinline__ int rp(int i, int e) {
    return (i == NN) ? e : (g_rowptr[i] + g_bsum[i >> 9]);
}

// ---- CSR bucket fill: 4 edges per thread ----------------------------------
__global__ void k_fill(const void* c0, const void* c1, int e) {
    const int* eptr = probe_is_edges(c0) ? (const int*)c0 : (const int*)c1;
    int i = (blockIdx.x * blockDim.x + threadIdx.x) * 4;
    if (i < e) {
        int4 s4 = *(const int4*)(eptr + i);
        int4 d4 = *(const int4*)(eptr + e + i);
        if ((unsigned)d4.x < (unsigned)NN)
            g_col[atomicAdd(&g_cur[d4.x], 1) + g_bsum[d4.x >> 9]] = s4.x;
        if ((unsigned)d4.y < (unsigned)NN)
            g_col[atomicAdd(&g_cur[d4.y], 1) + g_bsum[d4.y >> 9]] = s4.y;
        if ((unsigned)d4.z < (unsigned)NN)
            g_col[atomicAdd(&g_cur[d4.z], 1) + g_bsum[d4.z >> 9]] = s4.z;
        if ((unsigned)d4.w < (unsigned)NN)
            g_col[atomicAdd(&g_cur[d4.w], 1) + g_bsum[d4.w >> 9]] = s4.w;
    }
}

// ---- fp16 warp aggregation core: 8 edges in flight per iteration ----------
// Warp = node v. lane = eslot(2b)<<3 | fq(3b). After reduce, lanes 0..7 hold
// quad fq of  sum_{u in N(v)} in[u] + in[v]   (inputs pre-scaled by dinv[u]).
__device__ __forceinline__ float4 aggh(const __half* __restrict__ in,
                                       int v, int lane, int beg, int end) {
    int eslot = lane >> 3;
    int fq = lane & 7;
    float4 acc = make_float4(0.f, 0.f, 0.f, 0.f);
    for (int k = beg; k < end; k += 8) {
        int i0 = k + eslot;
        int i1 = k + 4 + eslot;
        int u0 = (i0 < end) ? g_col[i0] : -1;
        int u1 = (i1 < end) ? g_col[i1] : -1;
        if (u0 >= 0) {
            uint2 raw = *(const uint2*)(in + u0 * 32 + fq * 4);
            float2 fa = __half22float2(*(__half2*)&raw.x);
            float2 fb = __half22float2(*(__half2*)&raw.y);
            acc.x += fa.x; acc.y += fa.y; acc.z += fb.x; acc.w += fb.y;
        }
        if (u1 >= 0) {
            uint2 raw = *(const uint2*)(in + u1 * 32 + fq * 4);
            float2 fa = __half22float2(*(__half2*)&raw.x);
            float2 fb = __half22float2(*(__half2*)&raw.y);
            acc.x += fa.x; acc.y += fa.y; acc.z += fb.x; acc.w += fb.y;
        }
    }
    if (eslot == 0) {   // self-loop
        uint2 raw = *(const uint2*)(in + v * 32 + fq * 4);
        float2 fa = __half22float2(*(__half2*)&raw.x);
        float2 fb = __half22float2(*(__half2*)&raw.y);
        acc.x += fa.x; acc.y += fa.y; acc.z += fb.x; acc.w += fb.y;
    }
#pragma unroll
    for (int d = 16; d >= 8; d >>= 1) {
        acc.x += __shfl_down_sync(0xffffffffu, acc.x, d);
        acc.y += __shfl_down_sync(0xffffffffu, acc.y, d);
        acc.z += __shfl_down_sync(0xffffffffu, acc.z, d);
        acc.w += __shfl_down_sync(0xffffffffu, acc.w, d);
    }
    return acc;
}

// ---- layer 1 fused, warp-local: each warp owns TILE_W nodes ----------------
//  A) aggregate 8 nodes -> s_ax (warp-private smem)
//  B) h = relu(ax@W1+b1): weights in regs (loaded once per warp, coalesced
//     global), activations via conflict-free LDS.128 broadcasts
//  C) gs = dinv*(h@W2) -> g_gsh fp16, same pattern
__global__ __launch_bounds__(256) void k_l1(const float* __restrict__ W1,
                                            const float* __restrict__ b1,
                                            const float* __restrict__ W2,
                                            int n, int e) {
    __shared__ __align__(16) float s_ax[8][TILE_W][FIN];
    __shared__ __align__(16) float s_h[8][TILE_W][FHID];
    __shared__ float s_dv[8][TILE_W];

    int wl = threadIdx.x >> 5;
    int lane = threadIdx.x & 31;
    int base = (blockIdx.x * 8 + wl) * TILE_W;
    if (base >= n) return;

    // --- A: aggregate TILE_W nodes ---
#pragma unroll 1
    for (int j = 0; j < TILE_W; j++) {
        int v = base + j;
        if (v >= n) break;
        float4 acc = aggh(g_xsh, v, lane, rp(v, e), rp(v + 1, e));
        float dv = g_dinv[v];
        if (lane < 8) {
            float4 r;
            r.x = dv * acc.x; r.y = dv * acc.y;
            r.z = dv * acc.z; r.w = dv * acc.w;
            *(float4*)&s_ax[wl][j][lane * 4] = r;
        }
        if (lane == 0) s_dv[wl][j] = dv;
    }
    __syncwarp();

    // --- B: layer 1, weight column-pair (lane, lane+32) in registers ---
    unsigned long long w1p[32];
#pragma unroll
    for (int i = 0; i < 32; i++)
        w1p[i] = pk2(W1[i * 64 + lane], W1[i * 64 + 32 + lane]);
    unsigned long long bpair = pk2(b1[lane], b1[lane + 32]);

#pragma unroll 1
    for (int j = 0; j < TILE_W; j++) {
        if (base + j >= n) break;
        unsigned long long acc = bpair;
        const float4* axv = (const float4*)s_ax[wl][j];
#pragma unroll
        for (int i4 = 0; i4 < 8; i4++) {
            float4 x4 = axv[i4];          // LDS.128 broadcast
            FMA2(acc, dup2(x4.x), w1p[i4 * 4 + 0], acc);
            FMA2(acc, dup2(x4.y), w1p[i4 * 4 + 1], acc);
            FMA2(acc, dup2(x4.z), w1p[i4 * 4 + 2], acc);
            FMA2(acc, dup2(x4.w), w1p[i4 * 4 + 3], acc);
        }
        s_h[wl][j][lane]      = fmaxf(lo2(acc), 0.f);
        s_h[wl][j][lane + 32] = fmaxf(hi2(acc), 0.f);
    }
    __syncwarp();

    // --- C: layer 2, weight row-pair (2i, 2i+1) column lane in registers ---
    unsigned long long w2p[32];
#pragma unroll
    for (int i = 0; i < 32; i++)
        w2p[i] = pk2(W2[(2 * i) * 32 + lane], W2[(2 * i + 1) * 32 + lane]);

#pragma unroll 1
    for (int j = 0; j < TILE_W; j++) {
        int v = base + j;
        if (v >= n) break;
        unsigned long long acc = 0;
        const float4* hv = (const float4*)s_h[wl][j];
#pragma unroll
        for (int i4 = 0; i4 < 16; i4++) {
            float4 h4 = hv[i4];           // LDS.128 broadcast
            FMA2(acc, pk2(h4.x, h4.y), w2p[2 * i4 + 0], acc);
            FMA2(acc, pk2(h4.z, h4.w), w2p[2 * i4 + 1], acc);
        }
        float o = lo2(acc) + hi2(acc);
        g_gsh[v * 32 + lane] = __float2half_rn(s_dv[wl][j] * o);
    }
}

// ---- layer 2: out = dinv*(agg gs) + b2 -----------------------------------
__global__ __launch_bounds__(256) void k_l2(float* __restrict__ out,
                                            const float* __restrict__ b2,
                                            int n, int e) {
    int warp = (blockIdx.x * blockDim.x + threadIdx.x) >> 5;
    int lane = threadIdx.x & 31;
    if (warp >= n) return;
    int v = warp;

    float4 acc = aggh(g_gsh, v, lane, rp(v, e), rp(v + 1, e));
    if (lane < 8) {
        float dv = g_dinv[v];
        float4 bq = *(const float4*)(b2 + lane * 4);
        float4 r;
        r.x = dv * acc.x + bq.x;
        r.y = dv * acc.y + bq.y;
        r.z = dv * acc.z + bq.z;
        r.w = dv * acc.w + bq.w;
        *(float4*)(out + v * 32 + lane * 4) = r;
    }
}

// ---------------------------------------------------------------------------
extern "C" void kernel_launch(void* const* d_in, const int* in_sizes, int n_in,
                              void* d_out, int out_size) {
    // Resolve by element count: 3.2M x2 {x, edge_index} (probed on-device);
    // 2048 x2 W1 then W2; 64 b1; 32 b2.
    const void* big[2] = {nullptr, nullptr}; int nbig = 0;
    const float* W[2] = {nullptr, nullptr};  int nw = 0;
    const float* b1 = nullptr;
    const float* b2 = nullptr;
    for (int i = 0; i < n_in; i++) {
        int s = in_sizes[i];
        if (s == NN * FIN) { if (nbig < 2) big[nbig++] = d_in[i]; }
        else if (s == FIN * FHID) { if (nw < 2) W[nw++] = (const float*)d_in[i]; }
        else if (s == FHID) b1 = (const float*)d_in[i];
        else if (s == FOUT) b2 = (const float*)d_in[i];
    }
    const float* W1 = W[0];
    const float* W2 = W[1];
    float* out = (float*)d_out;

    const int n = NN;
    const int e = EE;
    int nb = (n + SCAN_B - 1) / SCAN_B;   // 196

    // zero g_deg via memset node (true device address, NOT the host shadow)
    void* degAddr = nullptr;
    cudaGetSymbolAddress(&degAddr, g_deg);
    cudaMemsetAsync(degAddr, 0, NN * sizeof(int));

    int eThreads = e / 4;
    k_count<<<(eThreads + 255) / 256, 256>>>(big[0], big[1], e);
    k_scan<<<nb, SCAN_B>>>(big[0], big[1], n, nb);
    k_fill<<<(eThreads + 255) / 256, 256>>>(big[0], big[1], e);

    int l1Grid = (n + 8 * TILE_W - 1) / (8 * TILE_W);   // 64 nodes per CTA
    k_l1<<<l1Grid, 256>>>(W1, b1, W2, n, e);
    int aggGrid = (n * 32 + 255) / 256;                 // warp per node
    k_l2<<<aggGrid, 256>>>(out, b2, n, e);
}

// round 8
// speedup vs baseline: 1.7057x; 1.2023x over previous
#include <cuda_runtime.h>
#include <cuda_fp16.h>

// Problem constants (fixed shapes per reference)
#define NN 100000
#define EE 1600000
#define FIN 32
#define FHID 64
#define FOUT 32

#define SCAN_B 512
#define NB_MAX 256   // ceil(100000/512)=196 <= 256
#define TILE_W 8     // nodes per warp in k_mlp

// Scratch (device globals — referenced ONLY from device code; host-side use of
// these symbols resolves to the host shadow object on GB300/ATS).
__device__ int    g_deg[NN];
__device__ int    g_rowptr[NN];        // block-local exclusive prefix of deg
__device__ int    g_cur[NN];           // fill cursor, initialized = g_rowptr
__device__ int    g_bsum[NB_MAX];      // per-block sums -> exclusive after last-block scan
__device__ float  g_dinv[NN];
__device__ int    g_col[EE];
__device__ int    g_scan_done = 0;     // last-block ticket (self-resetting)
__device__ __align__(16) __half g_xsh[NN * FIN];        // dinv[v]*x[v]   (fp16)
__device__ __align__(16) __half g_gsh[NN * FOUT];       // dinv[v]*(h@W2) (fp16)
__device__ __align__(16) float  g_ax[(NN + 64) * FIN];  // dinv*(agg xs)  (fp32, padded)

// packed f32x2 helpers
#define FMA2(d, a, b, c) \
    asm("fma.rn.f32x2 %0, %1, %2, %3;" : "=l"(d) : "l"(a), "l"(b), "l"(c))
__device__ __forceinline__ unsigned long long pk2(float a, float b) {
    float2 t = make_float2(a, b);
    return *(unsigned long long*)&t;
}
__device__ __forceinline__ unsigned long long dup2(float a) {
    unsigned long long r;
    asm("mov.b64 %0, {%1, %1};" : "=l"(r) : "r"(__float_as_uint(a)));
    return r;
}
__device__ __forceinline__ float lo2(unsigned long long v) {
    return __uint_as_float((unsigned)(v & 0xffffffffull));
}
__device__ __forceinline__ float hi2(unsigned long long v) {
    return __uint_as_float((unsigned)(v >> 32));
}

// ---------------------------------------------------------------------------
// Per-warp inline probe: which of {c0,c1} is edge_index? Edge words are
// unsigned < 100000; fp32 normal bit patterns are >= 2^23 or have sign bit.
__device__ __forceinline__ int probe_is_edges(const void* c0) {
    unsigned idx = (threadIdx.x & 31) * 99991u + (blockIdx.x & 1023) * 131u;
    unsigned v = ((const unsigned*)c0)[idx];  // < 3.2M
    return __all_sync(0xffffffffu, v < 100000u);
}

// ---- degree count: 4 edges per thread (int4) ------------------------------
__global__ void k_count(const void* c0, const void* c1, int e) {
    const int* eptr = probe_is_edges(c0) ? (const int*)c0 : (const int*)c1;
    int i = (blockIdx.x * blockDim.x + threadIdx.x) * 4;
    if (i < e) {
        int4 d4 = *(const int4*)(eptr + e + i);
        if ((unsigned)d4.x < (unsigned)NN) atomicAdd(&g_deg[d4.x], 1);
        if ((unsigned)d4.y < (unsigned)NN) atomicAdd(&g_deg[d4.y], 1);
        if ((unsigned)d4.z < (unsigned)NN) atomicAdd(&g_deg[d4.z], 1);
        if ((unsigned)d4.w < (unsigned)NN) atomicAdd(&g_deg[d4.w], 1);
    }
}

// ---- scan: block-exclusive scan of deg + dinv + fp16 pre-scale; the last
// block to finish also scans the 196 block sums (fused scanB).
__global__ __launch_bounds__(SCAN_B) void k_scan(const void* c0, const void* c1,
                                                 int n, int nb) {
    const float* xptr = probe_is_edges(c0) ? (const float*)c1 : (const float*)c0;
    __shared__ int   s[SCAN_B];
    __shared__ float sdinv[SCAN_B];
    __shared__ int   sB[NB_MAX];
    __shared__ bool  amLast;
    int t = threadIdx.x;
    int i = blockIdx.x * SCAN_B + t;
    int v = (i < n) ? g_deg[i] : 0;
    s[t] = v;
    __syncthreads();
    for (int o = 1; o < SCAN_B; o <<= 1) {
        int x = (t >= o) ? s[t - o] : 0;
        __syncthreads();
        s[t] += x;
        __syncthreads();
    }
    float d = rsqrtf((float)(v + 1));          // +1 self-loop
    if (i < n) {
        int excl = s[t] - v;
        g_rowptr[i] = excl;
        g_cur[i] = excl;                        // fill cursor
        g_dinv[i] = d;
    }
    sdinv[t] = d;
    if (t == SCAN_B - 1) g_bsum[blockIdx.x] = s[t];
    __syncthreads();

    // pre-scale: nodes [b0, b0+512) -> fp16 rows (4096 quads, 8 iters)
    int b0 = blockIdx.x * SCAN_B;
#pragma unroll
    for (int r = 0; r < 8; r++) {
        int ql = t + r * SCAN_B;               // local quad 0..4095
        int nl = ql >> 3;                      // local node
        int node = b0 + nl;
        if (node < n) {
            float4 p = ((const float4*)xptr)[node * 8 + (ql & 7)];
            float dd = sdinv[nl];
            __half2 h0 = __floats2half2_rn(p.x * dd, p.y * dd);
            __half2 h1 = __floats2half2_rn(p.z * dd, p.w * dd);
            uint2 packed;
            packed.x = *(unsigned*)&h0;
            packed.y = *(unsigned*)&h1;
            ((uint2*)g_xsh)[node * 8 + (ql & 7)] = packed;
        }
    }

    // last-block: exclusive scan of the nb block sums
    __threadfence();
    __syncthreads();
    if (t == 0) amLast = (atomicAdd(&g_scan_done, 1) == gridDim.x - 1);
    __syncthreads();
    if (amLast) {
        __threadfence();                        // acquire all bsum writes
        int bv = (t < NB_MAX && t < nb) ? g_bsum[t] : 0;
        if (t < NB_MAX) sB[t] = bv;
        __syncthreads();
        for (int o = 1; o < NB_MAX; o <<= 1) {
            int x = (t >= o && t < NB_MAX) ? sB[t - o] : 0;
            __syncthreads();
            if (t < NB_MAX) sB[t] += x;
            __syncthreads();
        }
        if (t < nb) g_bsum[t] = sB[t] - bv;     // exclusive block offsets
        if (t == 0) g_scan_done = 0;            // reset for next graph replay
    }
}

// global rowptr on the fly
__device__ __forceinline__ int rp(int i, int e) {
    return (i == NN) ? e : (g_rowptr[i] + g_bsum[i >> 9]);
}

// ---- CSR bucket fill: 4 edges per thread ----------------------------------
__global__ void k_fill(const void* c0, const void* c1, int e) {
    const int* eptr = probe_is_edges(c0) ? (const int*)c0 : (const int*)c1;
    int i = (blockIdx.x * blockDim.x + threadIdx.x) * 4;
    if (i < e) {
        int4 s4 = *(const int4*)(eptr + i);
        int4 d4 = *(const int4*)(eptr + e + i);
        if ((unsigned)d4.x < (unsigned)NN)
            g_col[atomicAdd(&g_cur[d4.x], 1) + g_bsum[d4.x >> 9]] = s4.x;
        if ((unsigned)d4.y < (unsigned)NN)
            g_col[atomicAdd(&g_cur[d4.y], 1) + g_bsum[d4.y >> 9]] = s4.y;
        if ((unsigned)d4.z < (unsigned)NN)
            g_col[atomicAdd(&g_cur[d4.z], 1) + g_bsum[d4.z >> 9]] = s4.z;
        if ((unsigned)d4.w < (unsigned)NN)
            g_col[atomicAdd(&g_cur[d4.w], 1) + g_bsum[d4.w >> 9]] = s4.w;
    }
}

// ---- fp16 warp aggregation core: 8 edges in flight per iteration ----------
// Warp = node v. lane = eslot(2b)<<3 | fq(3b). After reduce, lanes 0..7 hold
// quad fq of  sum_{u in N(v)} in[u] + in[v]   (inputs pre-scaled by dinv[u]).
__device__ __forceinline__ float4 aggh(const __half* __restrict__ in,
                                       int v, int lane, int beg, int end) {
    int eslot = lane >> 3;
    int fq = lane & 7;
    float4 acc = make_float4(0.f, 0.f, 0.f, 0.f);
    for (int k = beg; k < end; k += 8) {
        int i0 = k + eslot;
        int i1 = k + 4 + eslot;
        int u0 = (i0 < end) ? g_col[i0] : -1;
        int u1 = (i1 < end) ? g_col[i1] : -1;
        if (u0 >= 0) {
            uint2 raw = *(const uint2*)(in + u0 * 32 + fq * 4);
            float2 fa = __half22float2(*(__half2*)&raw.x);
            float2 fb = __half22float2(*(__half2*)&raw.y);
            acc.x += fa.x; acc.y += fa.y; acc.z += fb.x; acc.w += fb.y;
        }
        if (u1 >= 0) {
            uint2 raw = *(const uint2*)(in + u1 * 32 + fq * 4);
            float2 fa = __half22float2(*(__half2*)&raw.x);
            float2 fb = __half22float2(*(__half2*)&raw.y);
            acc.x += fa.x; acc.y += fa.y; acc.z += fb.x; acc.w += fb.y;
        }
    }
    if (eslot == 0) {   // self-loop
        uint2 raw = *(const uint2*)(in + v * 32 + fq * 4);
        float2 fa = __half22float2(*(__half2*)&raw.x);
        float2 fb = __half22float2(*(__half2*)&raw.y);
        acc.x += fa.x; acc.y += fa.y; acc.z += fb.x; acc.w += fb.y;
    }
#pragma unroll
    for (int d = 16; d >= 8; d >>= 1) {
        acc.x += __shfl_down_sync(0xffffffffu, acc.x, d);
        acc.y += __shfl_down_sync(0xffffffffu, acc.y, d);
        acc.z += __shfl_down_sync(0xffffffffu, acc.z, d);
        acc.w += __shfl_down_sync(0xffffffffu, acc.w, d);
    }
    return acc;
}

// ---- agg1: warp-per-node gather, low-regs/high-occ: ax = dinv*(agg xs) ----
__global__ __launch_bounds__(256) void k_agg1(int n, int e) {
    int warp = (blockIdx.x * blockDim.x + threadIdx.x) >> 5;
    int lane = threadIdx.x & 31;
    if (warp >= n) return;
    int v = warp;
    float4 acc = aggh(g_xsh, v, lane, rp(v, e), rp(v + 1, e));
    if (lane < 8) {
        float dv = g_dinv[v];
        float4 r;
        r.x = dv * acc.x; r.y = dv * acc.y;
        r.z = dv * acc.z; r.w = dv * acc.w;
        *(float4*)&g_ax[v * 32 + lane * 4] = r;
    }
}

// ---- mlp: dedicated, warp owns TILE_W nodes; weights in regs (phased so
// w1p/w2p lifetimes are disjoint); activations via conflict-free LDS.128
// broadcasts. gs = dinv*(relu(ax@W1+b1)@W2) -> fp16.
__global__ __launch_bounds__(256) void k_mlp(const float* __restrict__ W1,
                                             const float* __restrict__ b1,
                                             const float* __restrict__ W2,
                                             int n) {
    __shared__ __align__(16) float s_ax[8][TILE_W][FIN];
    __shared__ __align__(16) float s_h[8][TILE_W][FHID];

    int wl = threadIdx.x >> 5;
    int lane = threadIdx.x & 31;
    int base = (blockIdx.x * 8 + wl) * TILE_W;
    if (base >= n) return;

    // --- A: stage 8 node rows (g_ax is padded; OOB rows unused) ---
    {
        const float4* src = (const float4*)(g_ax + base * 32);
        float4* dst = (float4*)s_ax[wl];
        dst[lane]      = src[lane];
        dst[lane + 32] = src[lane + 32];
    }
    __syncwarp();

    // --- B: layer 1, weight column-pair (lane, lane+32) in registers ---
    {
        unsigned long long w1p[32];
#pragma unroll
        for (int i = 0; i < 32; i++)
            w1p[i] = pk2(W1[i * 64 + lane], W1[i * 64 + 32 + lane]);
        unsigned long long bpair = pk2(b1[lane], b1[lane + 32]);

#pragma unroll 1
        for (int j = 0; j < TILE_W; j++) {
            if (base + j >= n) break;
            unsigned long long acc = bpair;
            const float4* axv = (const float4*)s_ax[wl][j];
#pragma unroll
            for (int i4 = 0; i4 < 8; i4++) {
                float4 x4 = axv[i4];          // LDS.128 broadcast
                FMA2(acc, dup2(x4.x), w1p[i4 * 4 + 0], acc);
                FMA2(acc, dup2(x4.y), w1p[i4 * 4 + 1], acc);
                FMA2(acc, dup2(x4.z), w1p[i4 * 4 + 2], acc);
                FMA2(acc, dup2(x4.w), w1p[i4 * 4 + 3], acc);
            }
            s_h[wl][j][lane]      = fmaxf(lo2(acc), 0.f);
            s_h[wl][j][lane + 32] = fmaxf(hi2(acc), 0.f);
        }
    }
    __syncwarp();

    // --- C: layer 2, weight row-pair (2i, 2i+1) column lane in registers ---
    {
        unsigned long long w2p[32];
#pragma unroll
        for (int i = 0; i < 32; i++)
            w2p[i] = pk2(W2[(2 * i) * 32 + lane], W2[(2 * i + 1) * 32 + lane]);

#pragma unroll 1
        for (int j = 0; j < TILE_W; j++) {
            int v = base + j;
            if (v >= n) break;
            unsigned long long acc = 0;
            const float4* hv = (const float4*)s_h[wl][j];
#pragma unroll
            for (int i4 = 0; i4 < 16; i4++) {
                float4 h4 = hv[i4];           // LDS.128 broadcast
                FMA2(acc, pk2(h4.x, h4.y), w2p[2 * i4 + 0], acc);
                FMA2(acc, pk2(h4.z, h4.w), w2p[2 * i4 + 1], acc);
            }
            float o = lo2(acc) + hi2(acc);
            g_gsh[v * 32 + lane] = __float2half_rn(g_dinv[v] * o);
        }
    }
}

// ---- layer 2: out = dinv*(agg gs) + b2 -----------------------------------
__global__ __launch_bounds__(256) void k_l2(float* __restrict__ out,
                                            const float* __restrict__ b2,
                                            int n, int e) {
    int warp = (blockIdx.x * blockDim.x + threadIdx.x) >> 5;
    int lane = threadIdx.x & 31;
    if (warp >= n) return;
    int v = warp;

    float4 acc = aggh(g_gsh, v, lane, rp(v, e), rp(v + 1, e));
    if (lane < 8) {
        float dv = g_dinv[v];
        float4 bq = *(const float4*)(b2 + lane * 4);
        float4 r;
        r.x = dv * acc.x + bq.x;
        r.y = dv * acc.y + bq.y;
        r.z = dv * acc.z + bq.z;
        r.w = dv * acc.w + bq.w;
        *(float4*)(out + v * 32 + lane * 4) = r;
    }
}

// ---------------------------------------------------------------------------
extern "C" void kernel_launch(void* const* d_in, const int* in_sizes, int n_in,
                              void* d_out, int out_size) {
    // Resolve by element count: 3.2M x2 {x, edge_index} (probed on-device);
    // 2048 x2 W1 then W2; 64 b1; 32 b2.
    const void* big[2] = {nullptr, nullptr}; int nbig = 0;
    const float* W[2] = {nullptr, nullptr};  int nw = 0;
    const float* b1 = nullptr;
    const float* b2 = nullptr;
    for (int i = 0; i < n_in; i++) {
        int s = in_sizes[i];
        if (s == NN * FIN) { if (nbig < 2) big[nbig++] = d_in[i]; }
        else if (s == FIN * FHID) { if (nw < 2) W[nw++] = (const float*)d_in[i]; }
        else if (s == FHID) b1 = (const float*)d_in[i];
        else if (s == FOUT) b2 = (const float*)d_in[i];
    }
    const float* W1 = W[0];
    const float* W2 = W[1];
    float* out = (float*)d_out;

    const int n = NN;
    const int e = EE;
    int nb = (n + SCAN_B - 1) / SCAN_B;   // 196

    // zero g_deg via memset node (true device address, NOT the host shadow)
    void* degAddr = nullptr;
    cudaGetSymbolAddress(&degAddr, g_deg);
    cudaMemsetAsync(degAddr, 0, NN * sizeof(int));

    int eThreads = e / 4;
    k_count<<<(eThreads + 255) / 256, 256>>>(big[0], big[1], e);
    k_scan<<<nb, SCAN_B>>>(big[0], big[1], n, nb);
    k_fill<<<(eThreads + 255) / 256, 256>>>(big[0], big[1], e);

    int aggGrid = (n * 32 + 255) / 256;                 // warp per node
    k_agg1<<<aggGrid, 256>>>(n, e);
    int mlpGrid = (n + 8 * TILE_W - 1) / (8 * TILE_W);  // 64 nodes per CTA
    k_mlp<<<mlpGrid, 256>>>(W1, b1, W2, n);
    k_l2<<<aggGrid, 256>>>(out, b2, n, e);
}